// round 15
// baseline (speedup 1.0000x reference)
#include <cuda_runtime.h>
#include <math.h>

// ---------------------------------------------------------------------------
// MultiScaleAdaptiveElasticityLossWithLame
//   d_in[0]: deformation_field (2,3,160,192,160) f32
//   d_in[1]: image             (2,1,160,192,160) f32
//   out: scalar f32 loss
// ---------------------------------------------------------------------------

#define D0 160
#define H0 192
#define W0 160
#define D1 80
#define H1 96
#define W1 80
#define D2 40
#define H2 48
#define W2 40

#define VOL0 (D0*H0*W0)
#define VOL1 (D1*H1*W1)
#define VOL2 (D2*H2*W2)

// Total energy blocks across all 3 scales (each TOTAL is a multiple of 256):
//   e0: 2*160*192*40/256 = 9600, e1: 1200, e2: 150
#define E_BLOCKS_ALL (9600 + 1200 + 150)

__device__ float g_def1[2*3*VOL1];
__device__ float g_img1[2*1*VOL1];
__device__ float g_def2[2*3*VOL2];
__device__ float g_img2[2*1*VOL2];
__device__ double g_acc[3];          // zeroed at load; re-zeroed by last block
__device__ unsigned int g_cnt;       // completed energy blocks this replay

// ---------------------------------------------------------------------------
// Fused trilinear downsample (align_corners=True): def (6 planes) + img (2).
// One output per thread; index decomposition entirely from grid/block dims.
template<int Di, int Hi, int Wi, int Do, int Ho, int Wo>
__global__ void downsample_both(const float* __restrict__ def,
                                const float* __restrict__ img,
                                float* __restrict__ odef,
                                float* __restrict__ oimg,
                                float rD, float rH, float rW)
{
    constexpr int OVOL = Do * Ho * Wo;
    constexpr int IVOL = Di * Hi * Wi;

    int x = threadIdx.x;
    int y = blockIdx.x * blockDim.y + threadIdx.y;
    int z = blockIdx.y;
    int p = blockIdx.z;            // 0..7

    const float* in; float* outp;
    if (p < 6) { in = def + p * IVOL;       outp = odef + p * OVOL; }
    else       { in = img + (p - 6) * IVOL; outp = oimg + (p - 6) * OVOL; }

    float cz = (float)z * rD;
    float cy = (float)y * rH;
    float cx = (float)x * rW;
    int z0 = min((int)floorf(cz), Di - 1);
    int y0 = min((int)floorf(cy), Hi - 1);
    int x0 = min((int)floorf(cx), Wi - 1);
    float wz = cz - (float)z0;
    float wy = cy - (float)y0;
    float wx = cx - (float)x0;
    int z1 = min(z0 + 1, Di - 1);
    int y1 = min(y0 + 1, Hi - 1);
    int x1 = min(x0 + 1, Wi - 1);

    const float* pz0 = in + z0 * (Hi * Wi);
    const float* pz1 = in + z1 * (Hi * Wi);
    int oy0 = y0 * Wi, oy1 = y1 * Wi;

    float v000 = __ldg(pz0 + oy0 + x0), v001 = __ldg(pz0 + oy0 + x1);
    float v010 = __ldg(pz0 + oy1 + x0), v011 = __ldg(pz0 + oy1 + x1);
    float v100 = __ldg(pz1 + oy0 + x0), v101 = __ldg(pz1 + oy0 + x1);
    float v110 = __ldg(pz1 + oy1 + x0), v111 = __ldg(pz1 + oy1 + x1);

    float a00 = v000 * (1.f - wx) + v001 * wx;
    float a01 = v010 * (1.f - wx) + v011 * wx;
    float a10 = v100 * (1.f - wx) + v101 * wx;
    float a11 = v110 * (1.f - wx) + v111 * wx;
    float b0 = a00 * (1.f - wy) + a01 * wy;
    float b1 = a10 * (1.f - wy) + a11 * wy;
    outp[z * (Ho * Wo) + y * Wo + x] = b0 * (1.f - wz) + b1 * wz;
}

// ---------------------------------------------------------------------------
// torch.gradient of one field at 4 consecutive W positions (R9-proven form).
template<int D, int H, int W>
__device__ __forceinline__ void field_grads(const float* __restrict__ f,
                                            int d, int h, int w,
                                            float4& gD, float4& gH, float4& gW_)
{
    constexpr int sH = W;
    constexpr int sD = H * W;
    const float* base = f + d * sD + h * sH + w;

    float4 c = __ldg(reinterpret_cast<const float4*>(base));

    float xl = (w > 0)     ? __ldg(base - 1) : 0.f;
    float xr = (w + 4 < W) ? __ldg(base + 4) : 0.f;
    gW_.x = (w == 0)     ? (c.y - c.x) : 0.5f * (c.y - xl);
    gW_.y = 0.5f * (c.z - c.x);
    gW_.z = 0.5f * (c.w - c.y);
    gW_.w = (w + 4 == W) ? (c.w - c.z) : 0.5f * (xr - c.z);

    float4 hm = __ldg(reinterpret_cast<const float4*>(base - (h > 0     ? sH : 0)));
    float4 hp = __ldg(reinterpret_cast<const float4*>(base + (h < H - 1 ? sH : 0)));
    float sh = (h == 0 || h == H - 1) ? 1.0f : 0.5f;
    gH.x = sh * (hp.x - hm.x); gH.y = sh * (hp.y - hm.y);
    gH.z = sh * (hp.z - hm.z); gH.w = sh * (hp.w - hm.w);

    float4 dm = __ldg(reinterpret_cast<const float4*>(base - (d > 0     ? sD : 0)));
    float4 dp = __ldg(reinterpret_cast<const float4*>(base + (d < D - 1 ? sD : 0)));
    float sd = (d == 0 || d == D - 1) ? 1.0f : 0.5f;
    gD.x = sd * (dp.x - dm.x); gD.y = sd * (dp.y - dm.y);
    gD.z = sd * (dp.z - dm.z); gD.w = sd * (dp.w - dm.w);
}

__device__ __forceinline__ float4 f4add(float4 a, float4 b) {
    return make_float4(a.x + b.x, a.y + b.y, a.z + b.z, a.w + b.w);
}

// ---------------------------------------------------------------------------
// Flat energy kernel (R9-proven, 64 regs) + last-block finalize: the block
// that completes the global counter reads the fully-accumulated g_acc and
// writes the loss, removing the separate finalize launch from the tail.
template<int D, int H, int W>
__global__ void __launch_bounds__(256)
energy_flat(const float* __restrict__ def, const float* __restrict__ img,
            int scale_idx, float* __restrict__ out)
{
    constexpr int Wq = W >> 2;
    constexpr int TOTAL = 2 * D * H * Wq;
    constexpr int VOL = D * H * W;
    int i = blockIdx.x * 256 + threadIdx.x;

    float local = 0.f;
    if (i < TOTAL) {
        int xq = i % Wq; int t = i / Wq;
        int h = t % H;   t /= H;
        int d = t % D;
        int n = t / D;
        int w = xq << 2;

        const float* base = def + n * 3 * VOL;

        float4 Exx, Eyy, Ezz, Sxy, Sxz, Syz;   // Sab = 2*Eab
        {
            float4 gD, gH, gW;
            field_grads<D, H, W>(base, d, h, w, gD, gH, gW);   // u
            Exx = gD; Sxy = gH; Sxz = gW;
        }
        {
            float4 gD, gH, gW;
            field_grads<D, H, W>(base + VOL, d, h, w, gD, gH, gW);   // v
            Eyy = gH; Sxy = f4add(Sxy, gD); Syz = gW;
        }
        {
            float4 gD, gH, gW;
            field_grads<D, H, W>(base + 2 * VOL, d, h, w, gD, gH, gW);   // w
            Ezz = gW; Sxz = f4add(Sxz, gD); Syz = f4add(Syz, gH);
        }
        float4 g2;
        {
            float4 gD, gH, gW;
            field_grads<D, H, W>(img + n * VOL, d, h, w, gD, gH, gW);
            g2.x = gD.x * gD.x + gH.x * gH.x + gW.x * gW.x;
            g2.y = gD.y * gD.y + gH.y * gH.y + gW.y * gW.y;
            g2.z = gD.z * gD.z + gH.z * gH.z + gW.z * gW.z;
            g2.w = gD.w * gD.w + gH.w * gH.w + gW.w * gW.w;
        }

        const float* exx = reinterpret_cast<const float*>(&Exx);
        const float* eyy = reinterpret_cast<const float*>(&Eyy);
        const float* ezz = reinterpret_cast<const float*>(&Ezz);
        const float* sxy = reinterpret_cast<const float*>(&Sxy);
        const float* sxz = reinterpret_cast<const float*>(&Sxz);
        const float* syz = reinterpret_cast<const float*>(&Syz);
        const float* gg  = reinterpret_cast<const float*>(&g2);

        #pragma unroll
        for (int j = 0; j < 4; j++) {
            float exy = 0.5f * sxy[j];
            float exz = 0.5f * sxz[j];
            float eyz = 0.5f * syz[j];
            float tr = exx[j] + eyy[j] + ezz[j];
            float g = sqrtf(gg[j]);
            float lam = 1.0f + 0.5f * g;
            float mu  = 1.0f + 0.5f * g;
            float e = 0.5f * lam * tr * tr
                    + mu * (exx[j] * exx[j] + eyy[j] * eyy[j] + ezz[j] * ezz[j]
                            + 2.0f * (exy * exy + exz * exz + eyz * eyz));
            local += (1.0f + 0.1f * g) * e;
        }
    }

    #pragma unroll
    for (int o = 16; o > 0; o >>= 1)
        local += __shfl_down_sync(0xffffffffu, local, o);

    __shared__ float ws[8];
    int lane = threadIdx.x & 31;
    int wid  = threadIdx.x >> 5;
    if (lane == 0) ws[wid] = local;
    __syncthreads();
    if (wid == 0) {
        float s = (lane < 8) ? ws[lane] : 0.f;
        #pragma unroll
        for (int o = 4; o > 0; o >>= 1)
            s += __shfl_down_sync(0xffffffffu, s, o);
        if (lane == 0) {
            atomicAdd(&g_acc[scale_idx], (double)s);
            // Last-block finalize: fence our g_acc contribution, count up;
            // the final block sees all contributions (fence-ordered) and
            // emits the loss, then resets state for the next graph replay.
            __threadfence();
            unsigned int t = atomicAdd(&g_cnt, 1u);
            if (t == E_BLOCKS_ALL - 1) {
                double m0 = g_acc[0] / (2.0 * VOL0);
                double m1 = g_acc[1] / (2.0 * VOL1);
                double m2 = g_acc[2] / (2.0 * VOL2);
                out[0] = (float)(m0 + m1 + m2);
                g_acc[0] = 0.0; g_acc[1] = 0.0; g_acc[2] = 0.0;
                g_cnt = 0u;
            }
        }
    }
}

// ---------------------------------------------------------------------------
extern "C" void kernel_launch(void* const* d_in, const int* in_sizes, int n_in,
                              void* d_out, int out_size)
{
    const float* def = (const float*)d_in[0];
    const float* img = (const float*)d_in[1];
    float* out = (float*)d_out;

    float *p_def1, *p_img1, *p_def2, *p_img2;
    cudaGetSymbolAddress((void**)&p_def1, g_def1);
    cudaGetSymbolAddress((void**)&p_img1, g_img1);
    cudaGetSymbolAddress((void**)&p_def2, g_def2);
    cudaGetSymbolAddress((void**)&p_img2, g_img2);

    // Streams/events, created once on the (uncaptured) correctness call.
    static cudaStream_t s_a = nullptr, s_b = nullptr;
    static cudaEvent_t  e_fork = nullptr, e_ja = nullptr, e_jb = nullptr;
    if (s_a == nullptr) {
        cudaStreamCreateWithFlags(&s_a, cudaStreamNonBlocking);
        cudaStreamCreateWithFlags(&s_b, cudaStreamNonBlocking);
        cudaEventCreateWithFlags(&e_fork, cudaEventDisableTiming);
        cudaEventCreateWithFlags(&e_ja,   cudaEventDisableTiming);
        cudaEventCreateWithFlags(&e_jb,   cudaEventDisableTiming);
    }

    // Fork both side streams off the main stream's current position.
    cudaEventRecord(e_fork, 0);
    cudaStreamWaitEvent(s_a, e_fork, 0);
    cudaStreamWaitEvent(s_b, e_fork, 0);

    // ---- main stream FIRST: scale 0 (the critical path) ----
    {
        constexpr int T0 = 2 * D0 * H0 * (W0 / 4);
        energy_flat<D0, H0, W0><<<(T0 + 255) / 256, 256>>>(def, img, 0, out);
    }

    // ---- side stream A: ds1 -> e1 ----
    {
        float rD = (float)((double)(D0 - 1) / (double)(D1 - 1));
        float rH = (float)((double)(H0 - 1) / (double)(H1 - 1));
        float rW = (float)((double)(W0 - 1) / (double)(W1 - 1));
        dim3 blk(W1, 3);
        dim3 grd(H1 / 3, D1, 8);
        downsample_both<D0, H0, W0, D1, H1, W1>
            <<<grd, blk, 0, s_a>>>(def, img, p_def1, p_img1, rD, rH, rW);

        constexpr int T1 = 2 * D1 * H1 * (W1 / 4);
        energy_flat<D1, H1, W1><<<(T1 + 255) / 256, 256, 0, s_a>>>(p_def1, p_img1, 1, out);
    }

    // ---- side stream B: ds2 -> e2 (independent of chain A) ----
    {
        float rD = (float)((double)(D0 - 1) / (double)(D2 - 1));
        float rH = (float)((double)(H0 - 1) / (double)(H2 - 1));
        float rW = (float)((double)(W0 - 1) / (double)(W2 - 1));
        dim3 blk(W2, 6);
        dim3 grd(H2 / 6, D2, 8);
        downsample_both<D0, H0, W0, D2, H2, W2>
            <<<grd, blk, 0, s_b>>>(def, img, p_def2, p_img2, rD, rH, rW);

        constexpr int T2 = 2 * D2 * H2 * (W2 / 4);
        energy_flat<D2, H2, W2><<<(T2 + 255) / 256, 256, 0, s_b>>>(p_def2, p_img2, 2, out);
    }

    // Join both side streams back into the main stream (required for clean
    // graph capture; the loss itself is written by the last energy block).
    cudaEventRecord(e_ja, s_a);
    cudaEventRecord(e_jb, s_b);
    cudaStreamWaitEvent(0, e_ja, 0);
    cudaStreamWaitEvent(0, e_jb, 0);
}

// round 16
// speedup vs baseline: 1.0745x; 1.0745x over previous
#include <cuda_runtime.h>
#include <math.h>

// ---------------------------------------------------------------------------
// MultiScaleAdaptiveElasticityLossWithLame
//   d_in[0]: deformation_field (2,3,160,192,160) f32
//   d_in[1]: image             (2,1,160,192,160) f32
//   out: scalar f32 loss
// ---------------------------------------------------------------------------

#define D0 160
#define H0 192
#define W0 160
#define D1 80
#define H1 96
#define W1 80
#define D2 40
#define H2 48
#define W2 40

#define VOL0 (D0*H0*W0)
#define VOL1 (D1*H1*W1)
#define VOL2 (D2*H2*W2)

__device__ float g_def1[2*3*VOL1];
__device__ float g_img1[2*1*VOL1];
__device__ float g_def2[2*3*VOL2];
__device__ float g_img2[2*1*VOL2];
__device__ double g_acc[3];    // zeroed at load; re-zeroed by finalize each replay

// ---------------------------------------------------------------------------
// Fused trilinear downsample (align_corners=True): def (6 planes) + img (2).
// One output per thread; index decomposition entirely from grid/block dims.
template<int Di, int Hi, int Wi, int Do, int Ho, int Wo>
__global__ void downsample_both(const float* __restrict__ def,
                                const float* __restrict__ img,
                                float* __restrict__ odef,
                                float* __restrict__ oimg,
                                float rD, float rH, float rW)
{
    constexpr int OVOL = Do * Ho * Wo;
    constexpr int IVOL = Di * Hi * Wi;

    int x = threadIdx.x;
    int y = blockIdx.x * blockDim.y + threadIdx.y;
    int z = blockIdx.y;
    int p = blockIdx.z;            // 0..7

    const float* in; float* outp;
    if (p < 6) { in = def + p * IVOL;       outp = odef + p * OVOL; }
    else       { in = img + (p - 6) * IVOL; outp = oimg + (p - 6) * OVOL; }

    float cz = (float)z * rD;
    float cy = (float)y * rH;
    float cx = (float)x * rW;
    int z0 = min((int)floorf(cz), Di - 1);
    int y0 = min((int)floorf(cy), Hi - 1);
    int x0 = min((int)floorf(cx), Wi - 1);
    float wz = cz - (float)z0;
    float wy = cy - (float)y0;
    float wx = cx - (float)x0;
    int z1 = min(z0 + 1, Di - 1);
    int y1 = min(y0 + 1, Hi - 1);
    int x1 = min(x0 + 1, Wi - 1);

    const float* pz0 = in + z0 * (Hi * Wi);
    const float* pz1 = in + z1 * (Hi * Wi);
    int oy0 = y0 * Wi, oy1 = y1 * Wi;

    float v000 = __ldg(pz0 + oy0 + x0), v001 = __ldg(pz0 + oy0 + x1);
    float v010 = __ldg(pz0 + oy1 + x0), v011 = __ldg(pz0 + oy1 + x1);
    float v100 = __ldg(pz1 + oy0 + x0), v101 = __ldg(pz1 + oy0 + x1);
    float v110 = __ldg(pz1 + oy1 + x0), v111 = __ldg(pz1 + oy1 + x1);

    float a00 = v000 * (1.f - wx) + v001 * wx;
    float a01 = v010 * (1.f - wx) + v011 * wx;
    float a10 = v100 * (1.f - wx) + v101 * wx;
    float a11 = v110 * (1.f - wx) + v111 * wx;
    float b0 = a00 * (1.f - wy) + a01 * wy;
    float b1 = a10 * (1.f - wy) + a11 * wy;
    outp[z * (Ho * Wo) + y * Wo + x] = b0 * (1.f - wz) + b1 * wz;
}

// ---------------------------------------------------------------------------
// torch.gradient of one field at 4 consecutive W positions (R9-proven form).
template<int D, int H, int W>
__device__ __forceinline__ void field_grads(const float* __restrict__ f,
                                            int d, int h, int w,
                                            float4& gD, float4& gH, float4& gW_)
{
    constexpr int sH = W;
    constexpr int sD = H * W;
    const float* base = f + d * sD + h * sH + w;

    float4 c = __ldg(reinterpret_cast<const float4*>(base));

    float xl = (w > 0)     ? __ldg(base - 1) : 0.f;
    float xr = (w + 4 < W) ? __ldg(base + 4) : 0.f;
    gW_.x = (w == 0)     ? (c.y - c.x) : 0.5f * (c.y - xl);
    gW_.y = 0.5f * (c.z - c.x);
    gW_.z = 0.5f * (c.w - c.y);
    gW_.w = (w + 4 == W) ? (c.w - c.z) : 0.5f * (xr - c.z);

    float4 hm = __ldg(reinterpret_cast<const float4*>(base - (h > 0     ? sH : 0)));
    float4 hp = __ldg(reinterpret_cast<const float4*>(base + (h < H - 1 ? sH : 0)));
    float sh = (h == 0 || h == H - 1) ? 1.0f : 0.5f;
    gH.x = sh * (hp.x - hm.x); gH.y = sh * (hp.y - hm.y);
    gH.z = sh * (hp.z - hm.z); gH.w = sh * (hp.w - hm.w);

    float4 dm = __ldg(reinterpret_cast<const float4*>(base - (d > 0     ? sD : 0)));
    float4 dp = __ldg(reinterpret_cast<const float4*>(base + (d < D - 1 ? sD : 0)));
    float sd = (d == 0 || d == D - 1) ? 1.0f : 0.5f;
    gD.x = sd * (dp.x - dm.x); gD.y = sd * (dp.y - dm.y);
    gD.z = sd * (dp.z - dm.z); gD.w = sd * (dp.w - dm.w);
}

__device__ __forceinline__ float4 f4add(float4 a, float4 b) {
    return make_float4(a.x + b.x, a.y + b.y, a.z + b.z, a.w + b.w);
}

// ---------------------------------------------------------------------------
// Flat energy kernel with d-across-warps mapping: each block covers a 32-quad
// plane window x 8 consecutive d-planes (one per warp). Warps stay 512B-
// contiguous (coalescing preserved); warp w's dm/dp rows are warp w∓1's
// center rows -> L1 hits instead of cross-block L2.
//   Grid: (planeWindows) x (D/8) x (2 batches), block = 256.
//   planeWindows = H*(W/4)/32; divisibility: D%8==0, (H*W/4)%32==0 at all scales.
template<int D, int H, int W>
__global__ void __launch_bounds__(256)
energy_flat(const float* __restrict__ def, const float* __restrict__ img,
            int scale_idx)
{
    constexpr int Wq = W >> 2;
    constexpr int VOL = D * H * W;

    int lane = threadIdx.x & 31;
    int warp = threadIdx.x >> 5;

    int p  = blockIdx.x * 32 + lane;       // flat position in plane: h*Wq + xq
    int d  = blockIdx.y * 8 + warp;        // d-plane (one per warp)
    int n  = blockIdx.z;                   // batch

    int h  = p / Wq;
    int xq = p % Wq;
    int w  = xq << 2;

    float local = 0.f;
    {
        const float* base = def + n * 3 * VOL;

        float4 Exx, Eyy, Ezz, Sxy, Sxz, Syz;   // Sab = 2*Eab
        {
            float4 gD, gH, gW;
            field_grads<D, H, W>(base, d, h, w, gD, gH, gW);   // u
            Exx = gD; Sxy = gH; Sxz = gW;
        }
        {
            float4 gD, gH, gW;
            field_grads<D, H, W>(base + VOL, d, h, w, gD, gH, gW);   // v
            Eyy = gH; Sxy = f4add(Sxy, gD); Syz = gW;
        }
        {
            float4 gD, gH, gW;
            field_grads<D, H, W>(base + 2 * VOL, d, h, w, gD, gH, gW);   // w
            Ezz = gW; Sxz = f4add(Sxz, gD); Syz = f4add(Syz, gH);
        }
        float4 g2;
        {
            float4 gD, gH, gW;
            field_grads<D, H, W>(img + n * VOL, d, h, w, gD, gH, gW);
            g2.x = gD.x * gD.x + gH.x * gH.x + gW.x * gW.x;
            g2.y = gD.y * gD.y + gH.y * gH.y + gW.y * gW.y;
            g2.z = gD.z * gD.z + gH.z * gH.z + gW.z * gW.z;
            g2.w = gD.w * gD.w + gH.w * gH.w + gW.w * gW.w;
        }

        const float* exx = reinterpret_cast<const float*>(&Exx);
        const float* eyy = reinterpret_cast<const float*>(&Eyy);
        const float* ezz = reinterpret_cast<const float*>(&Ezz);
        const float* sxy = reinterpret_cast<const float*>(&Sxy);
        const float* sxz = reinterpret_cast<const float*>(&Sxz);
        const float* syz = reinterpret_cast<const float*>(&Syz);
        const float* gg  = reinterpret_cast<const float*>(&g2);

        #pragma unroll
        for (int j = 0; j < 4; j++) {
            float exy = 0.5f * sxy[j];
            float exz = 0.5f * sxz[j];
            float eyz = 0.5f * syz[j];
            float tr = exx[j] + eyy[j] + ezz[j];
            float g = sqrtf(gg[j]);
            float lam = 1.0f + 0.5f * g;
            float mu  = 1.0f + 0.5f * g;
            float e = 0.5f * lam * tr * tr
                    + mu * (exx[j] * exx[j] + eyy[j] * eyy[j] + ezz[j] * ezz[j]
                            + 2.0f * (exy * exy + exz * exz + eyz * eyz));
            local += (1.0f + 0.1f * g) * e;
        }
    }

    #pragma unroll
    for (int o = 16; o > 0; o >>= 1)
        local += __shfl_down_sync(0xffffffffu, local, o);

    __shared__ float ws[8];
    if (lane == 0) ws[warp] = local;
    __syncthreads();
    if (warp == 0) {
        float s = (lane < 8) ? ws[lane] : 0.f;
        #pragma unroll
        for (int o = 4; o > 0; o >>= 1)
            s += __shfl_down_sync(0xffffffffu, s, o);
        if (lane == 0)
            atomicAdd(&g_acc[scale_idx], (double)s);
    }
}

// ---------------------------------------------------------------------------
// Finalize: emit loss, then re-zero accumulators for the next replay.
__global__ void finalize_kernel(float* out) {
    double m0 = g_acc[0] / (2.0 * VOL0);
    double m1 = g_acc[1] / (2.0 * VOL1);
    double m2 = g_acc[2] / (2.0 * VOL2);
    out[0] = (float)(m0 + m1 + m2);
    g_acc[0] = 0.0; g_acc[1] = 0.0; g_acc[2] = 0.0;
}

// ---------------------------------------------------------------------------
extern "C" void kernel_launch(void* const* d_in, const int* in_sizes, int n_in,
                              void* d_out, int out_size)
{
    const float* def = (const float*)d_in[0];
    const float* img = (const float*)d_in[1];
    float* out = (float*)d_out;

    float *p_def1, *p_img1, *p_def2, *p_img2;
    cudaGetSymbolAddress((void**)&p_def1, g_def1);
    cudaGetSymbolAddress((void**)&p_img1, g_img1);
    cudaGetSymbolAddress((void**)&p_def2, g_def2);
    cudaGetSymbolAddress((void**)&p_img2, g_img2);

    // Streams/events, created once on the (uncaptured) correctness call.
    static cudaStream_t s_a = nullptr, s_b = nullptr;
    static cudaEvent_t  e_fork = nullptr, e_ja = nullptr, e_jb = nullptr;
    if (s_a == nullptr) {
        cudaStreamCreateWithFlags(&s_a, cudaStreamNonBlocking);
        cudaStreamCreateWithFlags(&s_b, cudaStreamNonBlocking);
        cudaEventCreateWithFlags(&e_fork, cudaEventDisableTiming);
        cudaEventCreateWithFlags(&e_ja,   cudaEventDisableTiming);
        cudaEventCreateWithFlags(&e_jb,   cudaEventDisableTiming);
    }

    // Fork both side streams off the main stream's current position.
    cudaEventRecord(e_fork, 0);
    cudaStreamWaitEvent(s_a, e_fork, 0);
    cudaStreamWaitEvent(s_b, e_fork, 0);

    // ---- main stream FIRST: scale 0 (the critical path) ----
    {
        dim3 g0(H0 * (W0 / 4) / 32, D0 / 8, 2);
        energy_flat<D0, H0, W0><<<g0, 256>>>(def, img, 0);
    }

    // ---- side stream A: ds1 -> e1 ----
    {
        float rD = (float)((double)(D0 - 1) / (double)(D1 - 1));
        float rH = (float)((double)(H0 - 1) / (double)(H1 - 1));
        float rW = (float)((double)(W0 - 1) / (double)(W1 - 1));
        dim3 blk(W1, 3);
        dim3 grd(H1 / 3, D1, 8);
        downsample_both<D0, H0, W0, D1, H1, W1>
            <<<grd, blk, 0, s_a>>>(def, img, p_def1, p_img1, rD, rH, rW);

        dim3 g1(H1 * (W1 / 4) / 32, D1 / 8, 2);
        energy_flat<D1, H1, W1><<<g1, 256, 0, s_a>>>(p_def1, p_img1, 1);
    }

    // ---- side stream B: ds2 -> e2 (independent of chain A) ----
    {
        float rD = (float)((double)(D0 - 1) / (double)(D2 - 1));
        float rH = (float)((double)(H0 - 1) / (double)(H2 - 1));
        float rW = (float)((double)(W0 - 1) / (double)(W2 - 1));
        dim3 blk(W2, 6);
        dim3 grd(H2 / 6, D2, 8);
        downsample_both<D0, H0, W0, D2, H2, W2>
            <<<grd, blk, 0, s_b>>>(def, img, p_def2, p_img2, rD, rH, rW);

        dim3 g2(H2 * (W2 / 4) / 32, D2 / 8, 2);
        energy_flat<D2, H2, W2><<<g2, 256, 0, s_b>>>(p_def2, p_img2, 2);
    }

    // Join both side streams, then finalize.
    cudaEventRecord(e_ja, s_a);
    cudaEventRecord(e_jb, s_b);
    cudaStreamWaitEvent(0, e_ja, 0);
    cudaStreamWaitEvent(0, e_jb, 0);
    finalize_kernel<<<1, 1>>>(out);
}